// round 6
// baseline (speedup 1.0000x reference)
#include <cuda_runtime.h>
#include <cuda_bf16.h>

#define N_NODES 100000
#define N_EDGES 1600000
#define F_IN 128
#define N_H 3
#define N_D 16
#define HD 48
#define NEG_SLOPE 0.2f

#define SCAN_B 256
#define NB ((N_NODES + SCAN_B - 1) / SCAN_B)   // 391

// Scratch (device globals)
__device__ float  g_feat[N_NODES * HD];     // projected features (N,48)
__device__ float4 g_el[N_NODES];            // (el0,el1,el2,_)
__device__ float4 g_er[N_NODES];            // (er0,er1,er2,_)
__device__ float4 g_edge[N_EDGES];          // packed (src_as_float, x0, x1, x2), grouped by dst
__device__ int    g_count[N_NODES];         // in-degree
__device__ int    g_off[N_NODES];           // CSR segment start
__device__ int    g_cur[N_NODES];           // scatter cursor
__device__ int    g_bsum[NB];               // per-block count sums
__device__ int    g_bbase[NB];              // exclusive scan of block sums

// ---------------------------------------------------------------------------
// Kernel 0: zero degree counters
// ---------------------------------------------------------------------------
__global__ void k_init() {
    int i = blockIdx.x * blockDim.x + threadIdx.x;
    if (i < N_NODES) g_count[i] = 0;
}

// ---------------------------------------------------------------------------
// Kernel 1: feat = x @ W^T (N x 48) + el/er logits.
// W in SMEM as float4 rows; k-loop unrolled 2x for LDG MLP.
// ---------------------------------------------------------------------------
__global__ __launch_bounds__(128) void k_gemm(const float* __restrict__ x,
                                              const float* __restrict__ W,
                                              const float* __restrict__ al,
                                              const float* __restrict__ ar)
{
    __shared__ float4 Ws4[HD][F_IN / 4];   // Ws4[j][i] = W[j*F_IN + 4i .. +3]
    __shared__ float als[HD], ars[HD];
    for (int i = threadIdx.x; i < HD * (F_IN / 4); i += 128) {
        Ws4[i / (F_IN / 4)][i % (F_IN / 4)] = ((const float4*)W)[i];
    }
    if (threadIdx.x < HD) {
        als[threadIdx.x] = al[threadIdx.x];
        ars[threadIdx.x] = ar[threadIdx.x];
    }
    __syncthreads();

    int t  = blockIdx.x * 128 + threadIdx.x;
    int n0 = 2 * t, n1 = 2 * t + 1;
    if (n0 >= N_NODES) return;
    bool has1 = (n1 < N_NODES);

    float acc0[HD], acc1[HD];
#pragma unroll
    for (int j = 0; j < HD; j++) { acc0[j] = 0.f; acc1[j] = 0.f; }

    const float4* x4 = (const float4*)x;
    int b0 = n0 * (F_IN / 4);
    int b1 = n1 * (F_IN / 4);

#pragma unroll 2
    for (int i = 0; i < F_IN / 4; i++) {
        float4 a = x4[b0 + i];
        float4 b = has1 ? x4[b1 + i] : make_float4(0.f, 0.f, 0.f, 0.f);
#pragma unroll
        for (int j = 0; j < HD; j++) {
            float4 w = Ws4[j][i];          // broadcast LDS.128
            acc0[j] = fmaf(a.x, w.x, fmaf(a.y, w.y, fmaf(a.z, w.z, fmaf(a.w, w.w, acc0[j]))));
            acc1[j] = fmaf(b.x, w.x, fmaf(b.y, w.y, fmaf(b.z, w.z, fmaf(b.w, w.w, acc1[j]))));
        }
    }

    {
        float el[N_H], er[N_H];
#pragma unroll
        for (int h = 0; h < N_H; h++) { el[h] = 0.f; er[h] = 0.f; }
#pragma unroll
        for (int h = 0; h < N_H; h++)
#pragma unroll
            for (int d = 0; d < N_D; d++) {
                el[h] = fmaf(acc0[h * N_D + d], als[h * N_D + d], el[h]);
                er[h] = fmaf(acc0[h * N_D + d], ars[h * N_D + d], er[h]);
            }
        g_el[n0] = make_float4(el[0], el[1], el[2], 0.f);
        g_er[n0] = make_float4(er[0], er[1], er[2], 0.f);
        float4* f4 = (float4*)(g_feat + (size_t)n0 * HD);
#pragma unroll
        for (int j = 0; j < HD / 4; j++)
            f4[j] = make_float4(acc0[4 * j], acc0[4 * j + 1], acc0[4 * j + 2], acc0[4 * j + 3]);
    }
    if (has1) {
        float el[N_H], er[N_H];
#pragma unroll
        for (int h = 0; h < N_H; h++) { el[h] = 0.f; er[h] = 0.f; }
#pragma unroll
        for (int h = 0; h < N_H; h++)
#pragma unroll
            for (int d = 0; d < N_D; d++) {
                el[h] = fmaf(acc1[h * N_D + d], als[h * N_D + d], el[h]);
                er[h] = fmaf(acc1[h * N_D + d], ars[h * N_D + d], er[h]);
            }
        g_el[n1] = make_float4(el[0], el[1], el[2], 0.f);
        g_er[n1] = make_float4(er[0], er[1], er[2], 0.f);
        float4* f4 = (float4*)(g_feat + (size_t)n1 * HD);
#pragma unroll
        for (int j = 0; j < HD / 4; j++)
            f4[j] = make_float4(acc1[4 * j], acc1[4 * j + 1], acc1[4 * j + 2], acc1[4 * j + 3]);
    }
}

// ---------------------------------------------------------------------------
// Kernel 2: in-degree histogram
// ---------------------------------------------------------------------------
__global__ void k_hist(const int* __restrict__ dst) {
    int e = blockIdx.x * blockDim.x + threadIdx.x;
    if (e >= N_EDGES) return;
    atomicAdd(&g_count[dst[e]], 1);
}

// ---------------------------------------------------------------------------
// Kernel 3a/3b/3c: hierarchical exclusive scan of g_count -> g_off, g_cur
// ---------------------------------------------------------------------------
__global__ __launch_bounds__(SCAN_B) void k_bsum() {
    __shared__ int sh[SCAN_B];
    int i = blockIdx.x * SCAN_B + threadIdx.x;
    sh[threadIdx.x] = (i < N_NODES) ? g_count[i] : 0;
    __syncthreads();
    for (int off = SCAN_B / 2; off > 0; off >>= 1) {
        if (threadIdx.x < off) sh[threadIdx.x] += sh[threadIdx.x + off];
        __syncthreads();
    }
    if (threadIdx.x == 0) g_bsum[blockIdx.x] = sh[0];
}

__global__ __launch_bounds__(512) void k_sscan() {
    __shared__ int sh[512];
    int t = threadIdx.x;
    sh[t] = (t < NB) ? g_bsum[t] : 0;
    __syncthreads();
    for (int off = 1; off < 512; off <<= 1) {
        int v = (t >= off) ? sh[t - off] : 0;
        __syncthreads();
        sh[t] += v;
        __syncthreads();
    }
    if (t < NB) g_bbase[t] = (t == 0) ? 0 : sh[t - 1];
}

__global__ __launch_bounds__(SCAN_B) void k_off() {
    __shared__ int sh[SCAN_B];
    int i = blockIdx.x * SCAN_B + threadIdx.x;
    int t = threadIdx.x;
    int c = (i < N_NODES) ? g_count[i] : 0;
    sh[t] = c;
    __syncthreads();
    for (int off = 1; off < SCAN_B; off <<= 1) {
        int v = (t >= off) ? sh[t - off] : 0;
        __syncthreads();
        sh[t] += v;
        __syncthreads();
    }
    if (i < N_NODES) {
        int excl = g_bbase[blockIdx.x] + sh[t] - c;
        g_off[i] = excl;
        g_cur[i] = excl;
    }
}

// ---------------------------------------------------------------------------
// Kernel 4: edge scatter — exp(leakyrelu(el[src]+er[dst])) per head,
// pack (src, x0, x1, x2) grouped by dst.
// Max-subtraction skipped: |e| <= ~4, softmax shift-invariant (fp32-safe).
// ---------------------------------------------------------------------------
__global__ void k_scatter(const int* __restrict__ src, const int* __restrict__ dst) {
    int e = blockIdx.x * blockDim.x + threadIdx.x;
    if (e >= N_EDGES) return;
    int s = src[e], d = dst[e];
    float4 L = g_el[s];
    float4 R = g_er[d];
    float v0 = L.x + R.x, v1 = L.y + R.y, v2 = L.z + R.z;
    v0 = v0 > 0.f ? v0 : NEG_SLOPE * v0;
    v1 = v1 > 0.f ? v1 : NEG_SLOPE * v1;
    v2 = v2 > 0.f ? v2 : NEG_SLOPE * v2;
    float x0 = __expf(v0), x1 = __expf(v1), x2 = __expf(v2);
    int pos = atomicAdd(&g_cur[d], 1);
    g_edge[pos] = make_float4(__int_as_float(s), x0, x1, x2);
}

// ---------------------------------------------------------------------------
// Kernel 5: per-dst aggregation, ONE WARP PER NODE.
// Lane l owns component l, and component l+32 when l<16 (heads: l>>4, and 2).
// 2-edge unroll x 2 components = 4 independent LDGs in flight per lane;
// warp-uniform trip count (no divergence); edge payload is a warp broadcast.
// ---------------------------------------------------------------------------
__global__ __launch_bounds__(256) void k_agg(const float* __restrict__ lin,
                                             float* __restrict__ out) {
    int d = (blockIdx.x * 256 + threadIdx.x) >> 5;
    if (d >= N_NODES) return;
    int lane = threadIdx.x & 31;
    int c0 = lane;               // 0..31
    int c1 = lane + 32;          // 32..63, valid when lane<16
    int h0 = lane >> 4;          // head for c0: 0 or 1
    bool has1 = (lane < 16);     // c1 head is always 2

    int beg = g_off[d];
    int cnt = g_count[d];
    int end = beg + cnt;

    float n0a = 0.f, n0b = 0.f, d0a = 0.f, d0b = 0.f;  // component c0
    float n1a = 0.f, n1b = 0.f, d1a = 0.f, d1b = 0.f;  // component c1 (head 2)

    int p = beg;
    for (; p + 2 <= end; p += 2) {
        float4 pk0 = g_edge[p];
        float4 pk1 = g_edge[p + 1];
        int s0 = __float_as_int(pk0.x);
        int s1 = __float_as_int(pk1.x);
        const float* r0 = g_feat + s0 * HD;
        const float* r1 = g_feat + s1 * HD;
        float f00 = __ldg(r0 + c0);
        float f10 = __ldg(r1 + c0);
        float f01 = has1 ? __ldg(r0 + c1) : 0.f;
        float f11 = has1 ? __ldg(r1 + c1) : 0.f;
        float a00 = (h0 == 0) ? pk0.y : pk0.z;
        float a10 = (h0 == 0) ? pk1.y : pk1.z;
        n0a = fmaf(a00, f00, n0a); d0a += a00;
        n0b = fmaf(a10, f10, n0b); d0b += a10;
        n1a = fmaf(pk0.w, f01, n1a); d1a += pk0.w;
        n1b = fmaf(pk1.w, f11, n1b); d1b += pk1.w;
    }
    if (p < end) {
        float4 pk = g_edge[p];
        int s = __float_as_int(pk.x);
        const float* r = g_feat + s * HD;
        float f0 = __ldg(r + c0);
        float f1 = has1 ? __ldg(r + c1) : 0.f;
        float a0 = (h0 == 0) ? pk.y : pk.z;
        n0a = fmaf(a0, f0, n0a); d0a += a0;
        n1a = fmaf(pk.w, f1, n1a); d1a += pk.w;
    }

    float num0 = n0a + n0b, den0 = d0a + d0b;
    float num1 = n1a + n1b, den1 = d1a + d1b;
    float msg0 = (cnt > 0) ? (num0 / den0) : 0.f;
    float msg1 = (cnt > 0) ? (num1 / den1) : 0.f;
    float l = lin[d];
    float fd0 = g_feat[d * HD + c0];
    out[d * HD + c0] = (1.f - l) * msg0 + l * fd0;
    if (has1) {
        float fd1 = g_feat[d * HD + c1];
        out[d * HD + c1] = (1.f - l) * msg1 + l * fd1;
    }
}

// ---------------------------------------------------------------------------
extern "C" void kernel_launch(void* const* d_in, const int* in_sizes, int n_in,
                              void* d_out, int out_size) {
    const float* x   = (const float*)d_in[0];
    const float* W   = (const float*)d_in[1];
    const float* al  = (const float*)d_in[2];
    const float* ar  = (const float*)d_in[3];
    const float* lin = (const float*)d_in[4];
    const int*   src = (const int*)d_in[5];
    const int*   dst = (const int*)d_in[6];
    float* out = (float*)d_out;

    k_init<<<(N_NODES + 255) / 256, 256>>>();
    k_gemm<<<(N_NODES + 255) / 256, 128>>>(x, W, al, ar);
    k_hist<<<(N_EDGES + 255) / 256, 256>>>(dst);
    k_bsum<<<NB, SCAN_B>>>();
    k_sscan<<<1, 512>>>();
    k_off<<<NB, SCAN_B>>>();
    k_scatter<<<(N_EDGES + 255) / 256, 256>>>(src, dst);

    // warp per node: 8 nodes per 256-thread block
    k_agg<<<(N_NODES + 7) / 8, 256>>>(lin, out);
}